// round 12
// baseline (speedup 1.0000x reference)
#include <cuda_runtime.h>
#include <cuda_bf16.h>
#include <math.h>
#include <stdint.h>

// Problem constants
#define B_  4
#define L_  2048
#define D_  1024
#define H_  16
#define HD_ 64
#define M_TOT (B_ * L_)          // 8192 rows for all projection GEMMs

// ---------------------------------------------------------------------------
// Scratch (allocation-free rule: __device__ globals)
// ---------------------------------------------------------------------------
__device__ float g_Q[(size_t)M_TOT * D_];
__device__ float g_K[(size_t)M_TOT * D_];
__device__ float g_V[(size_t)M_TOT * D_];
__device__ float g_C[(size_t)M_TOT * D_];
// bf16 3-term split planes, packed 2 bf16 per u32 along K (512 u32 per row).
__device__ uint32_t g_asp[(size_t)4 * 3 * M_TOT * 512];   // q,k,v,ctx
__device__ uint32_t g_wsp[(size_t)4 * 3 * 1024 * 512];    // Wq,Wk,Wv,Wo

// ---------------------------------------------------------------------------
// split3: fp32 -> 3 bf16 planes, packed 2-per-u32 along K. x = b0+b1+b2.
// ---------------------------------------------------------------------------
__global__ void split3_kernel(const float* __restrict__ X, uint32_t* __restrict__ P,
                              size_t plane, int n)
{
    int i = blockIdx.x * blockDim.x + threadIdx.x;
    if (i >= n) return;
    float2 v = *(const float2*)(X + (size_t)2 * i);
    unsigned short a0, a1, a2, b0, b1, b2;
    {
        float x = v.x;
        __nv_bfloat16 h = __float2bfloat16_rn(x); a0 = __bfloat16_as_ushort(h);
        float r = x - __bfloat162float(h);
        h = __float2bfloat16_rn(r); a1 = __bfloat16_as_ushort(h);
        r = r - __bfloat162float(h);
        h = __float2bfloat16_rn(r); a2 = __bfloat16_as_ushort(h);
    }
    {
        float x = v.y;
        __nv_bfloat16 h = __float2bfloat16_rn(x); b0 = __bfloat16_as_ushort(h);
        float r = x - __bfloat162float(h);
        h = __float2bfloat16_rn(r); b1 = __bfloat16_as_ushort(h);
        r = r - __bfloat162float(h);
        h = __float2bfloat16_rn(r); b2 = __bfloat16_as_ushort(h);
    }
    P[i]             = (uint32_t)a0 | ((uint32_t)b0 << 16);
    P[plane + i]     = (uint32_t)a1 | ((uint32_t)b1 << 16);
    P[2 * plane + i] = (uint32_t)a2 | ((uint32_t)b2 << 16);
}

// ---------------------------------------------------------------------------
// bf16 m16n8k16 mma.sync (baseline PTX, no 'a'-target features)
// ---------------------------------------------------------------------------
__device__ __forceinline__ void mma_bf16(
    float& c0, float& c1, float& c2, float& c3,
    uint32_t a0, uint32_t a1, uint32_t a2, uint32_t a3,
    uint32_t b0, uint32_t b1)
{
    asm volatile(
        "mma.sync.aligned.m16n8k16.row.col.f32.bf16.bf16.f32 "
        "{%0,%1,%2,%3}, {%4,%5,%6,%7}, {%8,%9}, {%0,%1,%2,%3};\n"
        : "+f"(c0), "+f"(c1), "+f"(c2), "+f"(c3)
        : "r"(a0), "r"(a1), "r"(a2), "r"(a3), "r"(b0), "r"(b1));
}

// ---------------------------------------------------------------------------
// GEMM: C[m][n] = sum_k A[m][k]*W[n][k] + bias[n] via bf16 3-split mma.sync.
// Inputs are pre-split packed planes (g_asp/g_wsp): word w of row r holds
// elems 2w, 2w+1 -> exactly the m16n8k16 k-pair format.
// CTA tile 128x128, BK=16 elems (8 words); 8 warps (warp_m 0..1 x warp_n 0..3),
// warp tile 64x32 via 4x4 m16n8k16 MMAs, 6 products per tile-pair:
// (00,01,10,11,02,20); dropped terms ~2^-24.
// SMEM: [2 buf][2 mat][128 rows][28 words]; stride 28 -> all-32-banks-distinct
// fragment loads; staging uint4s perfectly quad-balanced. 57344 B dynamic.
// Mainloop: zero cvt; 6 uint4 global loads prefetched per tile per thread.
// ---------------------------------------------------------------------------
#define TSW 28                     // SMEM row stride in words
#define GBW (128 * TSW)            // words per matrix per buffer = 3584

__global__ __launch_bounds__(256, 1) void gemm_bf16s_bias(
    const uint32_t* __restrict__ Asp, const uint32_t* __restrict__ Wsp,
    size_t PA, size_t PW,
    const float* __restrict__ bias, float* __restrict__ C)
{
    extern __shared__ uint32_t gsm[];
    uint32_t* As = gsm;              // [2][GBW]
    uint32_t* Ws = gsm + 2 * GBW;    // [2][GBW]

    const int tid    = threadIdx.x;
    const int warp   = tid >> 5;
    const int lane   = tid & 31;
    const int g      = lane >> 2;    // 0..7
    const int tig    = lane & 3;     // 0..3
    const int warp_m = warp >> 2;    // 0..1 -> 64-row slab
    const int warp_n = warp & 3;     // 0..3 -> 32-col slab

    const int m0 = blockIdx.y * 128;
    const int n0 = blockIdx.x * 128;

    // Staging coords: per plane per matrix: 1 uint4 per thread
    const int srow = tid >> 1;            // 0..127
    const int sw   = (tid & 1) * 4;       // word 0 or 4 within the 8-word chunk

    float c[4][4][4];
#pragma unroll
    for (int i = 0; i < 4; i++)
#pragma unroll
        for (int j = 0; j < 4; j++)
#pragma unroll
            for (int r = 0; r < 4; r++) c[i][j][r] = 0.0f;

    // Prologue: stage tile 0
#pragma unroll
    for (int t = 0; t < 3; t++) {
        *(uint4*)&As[srow * TSW + t * 8 + sw] =
            *(const uint4*)(Asp + t * PA + (size_t)(m0 + srow) * 512 + sw);
        *(uint4*)&Ws[srow * TSW + t * 8 + sw] =
            *(const uint4*)(Wsp + t * PW + (size_t)(n0 + srow) * 512 + sw);
    }
    __syncthreads();

    for (int kt = 0; kt < 64; kt++) {
        const int cur = kt & 1;
        const bool have_next = (kt + 1 < 64);

        uint4 na[3], nw[3];
        if (have_next) {
            const int kw = (kt + 1) * 8 + sw;
#pragma unroll
            for (int t = 0; t < 3; t++) {
                na[t] = *(const uint4*)(Asp + t * PA + (size_t)(m0 + srow) * 512 + kw);
                nw[t] = *(const uint4*)(Wsp + t * PW + (size_t)(n0 + srow) * 512 + kw);
            }
        }

        // ---- Compute: one k16 step ----
        const uint32_t* Ab = As + cur * GBW;
        const uint32_t* Wb = Ws + cur * GBW;

        uint32_t a0f[4][4], a1f[4][4];   // planes 0, 1 A-fragments
#pragma unroll
        for (int mt = 0; mt < 4; mt++) {
            const int r  = warp_m * 64 + mt * 16 + g;
            const int ba = r * TSW + tig;
            a0f[mt][0] = Ab[ba];
            a0f[mt][1] = Ab[ba + 8 * TSW];
            a0f[mt][2] = Ab[ba + 4];
            a0f[mt][3] = Ab[ba + 8 * TSW + 4];
            a1f[mt][0] = Ab[ba + 8];
            a1f[mt][1] = Ab[ba + 8 * TSW + 8];
            a1f[mt][2] = Ab[ba + 12];
            a1f[mt][3] = Ab[ba + 8 * TSW + 12];
        }
        // Pass 1: products (00),(01),(10),(11),(02)
#pragma unroll
        for (int nt = 0; nt < 4; nt++) {
            const int n  = warp_n * 32 + nt * 8 + g;
            const int bb = n * TSW + tig;
            uint32_t b00 = Wb[bb],      b01 = Wb[bb + 4];
            uint32_t b10 = Wb[bb + 8],  b11 = Wb[bb + 12];
            uint32_t b20 = Wb[bb + 16], b21 = Wb[bb + 20];
#pragma unroll
            for (int mt = 0; mt < 4; mt++) {
                mma_bf16(c[mt][nt][0], c[mt][nt][1], c[mt][nt][2], c[mt][nt][3],
                         a0f[mt][0], a0f[mt][1], a0f[mt][2], a0f[mt][3], b00, b01);
                mma_bf16(c[mt][nt][0], c[mt][nt][1], c[mt][nt][2], c[mt][nt][3],
                         a0f[mt][0], a0f[mt][1], a0f[mt][2], a0f[mt][3], b10, b11);
                mma_bf16(c[mt][nt][0], c[mt][nt][1], c[mt][nt][2], c[mt][nt][3],
                         a1f[mt][0], a1f[mt][1], a1f[mt][2], a1f[mt][3], b00, b01);
                mma_bf16(c[mt][nt][0], c[mt][nt][1], c[mt][nt][2], c[mt][nt][3],
                         a1f[mt][0], a1f[mt][1], a1f[mt][2], a1f[mt][3], b10, b11);
                mma_bf16(c[mt][nt][0], c[mt][nt][1], c[mt][nt][2], c[mt][nt][3],
                         a0f[mt][0], a0f[mt][1], a0f[mt][2], a0f[mt][3], b20, b21);
            }
        }
        // Pass 2: product (20) — reuse a0f storage for plane-2 A-fragments
#pragma unroll
        for (int mt = 0; mt < 4; mt++) {
            const int r  = warp_m * 64 + mt * 16 + g;
            const int ba = r * TSW + tig;
            a0f[mt][0] = Ab[ba + 16];
            a0f[mt][1] = Ab[ba + 8 * TSW + 16];
            a0f[mt][2] = Ab[ba + 20];
            a0f[mt][3] = Ab[ba + 8 * TSW + 20];
        }
#pragma unroll
        for (int nt = 0; nt < 4; nt++) {
            const int n  = warp_n * 32 + nt * 8 + g;
            const int bb = n * TSW + tig;
            uint32_t b00 = Wb[bb], b01 = Wb[bb + 4];
#pragma unroll
            for (int mt = 0; mt < 4; mt++)
                mma_bf16(c[mt][nt][0], c[mt][nt][1], c[mt][nt][2], c[mt][nt][3],
                         a0f[mt][0], a0f[mt][1], a0f[mt][2], a0f[mt][3], b00, b01);
        }

        if (have_next) {
            const int nb = 1 - cur;
#pragma unroll
            for (int t = 0; t < 3; t++) {
                *(uint4*)&As[nb * GBW + srow * TSW + t * 8 + sw] = na[t];
                *(uint4*)&Ws[nb * GBW + srow * TSW + t * 8 + sw] = nw[t];
            }
            __syncthreads();
        }
    }

    // Epilogue: bias add + float2 stores (audited mapping, same frag layout)
#pragma unroll
    for (int nt = 0; nt < 4; nt++) {
        const int col = n0 + warp_n * 32 + nt * 8 + 2 * tig;
        const float b0v = bias[col];
        const float b1v = bias[col + 1];
#pragma unroll
        for (int mt = 0; mt < 4; mt++) {
            const int row = m0 + warp_m * 64 + mt * 16 + g;
            *(float2*)(C + (size_t)row * 1024 + col) =
                make_float2(c[mt][nt][0] + b0v, c[mt][nt][1] + b1v);
            *(float2*)(C + (size_t)(row + 8) * 1024 + col) =
                make_float2(c[mt][nt][2] + b0v, c[mt][nt][3] + b1v);
        }
    }
}

// ---------------------------------------------------------------------------
// tf32 helpers (attention path)
// ---------------------------------------------------------------------------
__device__ __forceinline__ float tf32r(float x) {
    uint32_t r;
    asm("cvt.rna.tf32.f32 %0, %1;" : "=r"(r) : "f"(x));
    return __uint_as_float(r);
}
__device__ __forceinline__ void mma_tf32(
    float& c0, float& c1, float& c2, float& c3,
    uint32_t a0, uint32_t a1, uint32_t a2, uint32_t a3,
    uint32_t b0, uint32_t b1)
{
    asm volatile(
        "mma.sync.aligned.m16n8k8.row.col.f32.tf32.tf32.f32 "
        "{%0,%1,%2,%3}, {%4,%5,%6,%7}, {%8,%9}, {%0,%1,%2,%3};\n"
        : "+f"(c0), "+f"(c1), "+f"(c2), "+f"(c3)
        : "r"(a0), "r"(a1), "r"(a2), "r"(a3), "r"(b0), "r"(b1));
}

// ---------------------------------------------------------------------------
// Flash attention, split-tf32 mma.sync — measured-best R7 form (2682us run).
// ---------------------------------------------------------------------------
#define AST 68
#define ATILE 4352          // 64*68

__global__ __launch_bounds__(256) void attn_tc(
    const float* __restrict__ Q, const float* __restrict__ K,
    const float* __restrict__ V, float* __restrict__ O)
{
    extern __shared__ float sm[];
    float* Qhi = sm;
    float* Qlo = sm + ATILE;
    float* Khi = sm + 2 * ATILE;    // aliased as P after S-phase
    float* Klo = sm + 3 * ATILE;
    float* Vhi = sm + 4 * ATILE;
    float* Vlo = sm + 5 * ATILE;
    float* Pbuf = Khi;
    float* maxbuf = sm + 6 * ATILE;        // [2][64]
    float* sumbuf = maxbuf + 128;          // [2][64]

    const int tid  = threadIdx.x;
    const int warp = tid >> 5;
    const int lane = tid & 31;
    const int g    = lane >> 2;
    const int tig  = lane & 3;
    const int warp_m = warp >> 1;
    const int warp_n = warp & 1;
    const int m0 = warp_m * 16;
    const int nb = warp_n * 32;

    const int q0 = blockIdx.x * 64;
    const int bh = blockIdx.y;
    const int b  = bh / H_;
    const int h  = bh % H_;

    const float* Qb = Q + (size_t)b * L_ * D_ + h * HD_;
    const float* Kb = K + (size_t)b * L_ * D_ + h * HD_;
    const float* Vb = V + (size_t)b * L_ * D_ + h * HD_;

#pragma unroll
    for (int t = 0; t < 4; t++) {
        int idx = tid + t * 256;
        int row = idx >> 4;
        int d0  = (idx & 15) << 2;
        float4 v = *(const float4*)(Qb + (size_t)(q0 + row) * D_ + d0);
        v.x *= 0.125f; v.y *= 0.125f; v.z *= 0.125f; v.w *= 0.125f;
        float4 hi = make_float4(tf32r(v.x), tf32r(v.y), tf32r(v.z), tf32r(v.w));
        float4 lo = make_float4(tf32r(v.x - hi.x), tf32r(v.y - hi.y),
                                tf32r(v.z - hi.z), tf32r(v.w - hi.w));
        *(float4*)&Qhi[row * AST + d0] = hi;
        *(float4*)&Qlo[row * AST + d0] = lo;
    }

    float mi0 = -INFINITY, mi1 = -INFINITY, li0 = 0.0f, li1 = 0.0f;
    float oacc[4][4];
#pragma unroll
    for (int nt = 0; nt < 4; nt++)
#pragma unroll
        for (int r = 0; r < 4; r++) oacc[nt][r] = 0.0f;

    for (int kv0 = 0; kv0 < L_; kv0 += 64) {
        __syncthreads();   // (A)

#pragma unroll
        for (int t = 0; t < 4; t++) {
            int idx = tid + t * 256;
            int row = idx >> 4;
            int d0  = (idx & 15) << 2;
            float4 kv = *(const float4*)(Kb + (size_t)(kv0 + row) * D_ + d0);
            float4 khi = make_float4(tf32r(kv.x), tf32r(kv.y), tf32r(kv.z), tf32r(kv.w));
            float4 klo = make_float4(tf32r(kv.x - khi.x), tf32r(kv.y - khi.y),
                                     tf32r(kv.z - khi.z), tf32r(kv.w - khi.w));
            *(float4*)&Khi[row * AST + d0] = khi;
            *(float4*)&Klo[row * AST + d0] = klo;
            float4 vv = *(const float4*)(Vb + (size_t)(kv0 + row) * D_ + d0);
            float4 vhi = make_float4(tf32r(vv.x), tf32r(vv.y), tf32r(vv.z), tf32r(vv.w));
            float4 vlo = make_float4(tf32r(vv.x - vhi.x), tf32r(vv.y - vhi.y),
                                     tf32r(vv.z - vhi.z), tf32r(vv.w - vhi.w));
            *(float4*)&Vhi[row * AST + d0] = vhi;
            *(float4*)&Vlo[row * AST + d0] = vlo;
        }
        __syncthreads();   // (B)

        float sacc[4][4];
#pragma unroll
        for (int nt = 0; nt < 4; nt++)
#pragma unroll
            for (int r = 0; r < 4; r++) sacc[nt][r] = 0.0f;

#pragma unroll
        for (int k8 = 0; k8 < 8; k8++) {
            const int kb = k8 * 8;
            const int ra = (m0 + g) * AST + kb + tig;
            const int rb = (m0 + g + 8) * AST + kb + tig;
            uint32_t ah0 = __float_as_uint(Qhi[ra]);
            uint32_t ah1 = __float_as_uint(Qhi[rb]);
            uint32_t ah2 = __float_as_uint(Qhi[ra + 4]);
            uint32_t ah3 = __float_as_uint(Qhi[rb + 4]);
            uint32_t al0 = __float_as_uint(Qlo[ra]);
            uint32_t al1 = __float_as_uint(Qlo[rb]);
            uint32_t al2 = __float_as_uint(Qlo[ra + 4]);
            uint32_t al3 = __float_as_uint(Qlo[rb + 4]);
#pragma unroll
            for (int nt = 0; nt < 4; nt++) {
                const int rn = (nb + nt * 8 + g) * AST + kb + tig;
                uint32_t bh0 = __float_as_uint(Khi[rn]);
                uint32_t bh1 = __float_as_uint(Khi[rn + 4]);
                uint32_t bl0 = __float_as_uint(Klo[rn]);
                uint32_t bl1 = __float_as_uint(Klo[rn + 4]);
                mma_tf32(sacc[nt][0], sacc[nt][1], sacc[nt][2], sacc[nt][3],
                         ah0, ah1, ah2, ah3, bh0, bh1);
                mma_tf32(sacc[nt][0], sacc[nt][1], sacc[nt][2], sacc[nt][3],
                         ah0, ah1, ah2, ah3, bl0, bl1);
                mma_tf32(sacc[nt][0], sacc[nt][1], sacc[nt][2], sacc[nt][3],
                         al0, al1, al2, al3, bh0, bh1);
            }
        }

        float mx0 = -INFINITY, mx1 = -INFINITY;
#pragma unroll
        for (int nt = 0; nt < 4; nt++) {
            mx0 = fmaxf(mx0, fmaxf(sacc[nt][0], sacc[nt][1]));
            mx1 = fmaxf(mx1, fmaxf(sacc[nt][2], sacc[nt][3]));
        }
        mx0 = fmaxf(mx0, __shfl_xor_sync(0xffffffffu, mx0, 1));
        mx0 = fmaxf(mx0, __shfl_xor_sync(0xffffffffu, mx0, 2));
        mx1 = fmaxf(mx1, __shfl_xor_sync(0xffffffffu, mx1, 1));
        mx1 = fmaxf(mx1, __shfl_xor_sync(0xffffffffu, mx1, 2));
        if (tig == 0) {
            maxbuf[warp_n * 64 + m0 + g]     = mx0;
            maxbuf[warp_n * 64 + m0 + g + 8] = mx1;
        }
        __syncthreads();   // (C)

        const float mn0 = fmaxf(mi0, fmaxf(maxbuf[m0 + g], maxbuf[64 + m0 + g]));
        const float mn1 = fmaxf(mi1, fmaxf(maxbuf[m0 + g + 8], maxbuf[64 + m0 + g + 8]));
        const float sc0 = __expf(mi0 - mn0);
        const float sc1 = __expf(mi1 - mn1);
        mi0 = mn0; mi1 = mn1;

        float ps0 = 0.0f, ps1 = 0.0f;
#pragma unroll
        for (int nt = 0; nt < 4; nt++) {
            sacc[nt][0] = __expf(sacc[nt][0] - mn0);
            sacc[nt][1] = __expf(sacc[nt][1] - mn0);
            sacc[nt][2] = __expf(sacc[nt][2] - mn1);
            sacc[nt][3] = __expf(sacc[nt][3] - mn1);
            ps0 += sacc[nt][0] + sacc[nt][1];
            ps1 += sacc[nt][2] + sacc[nt][3];
        }
        ps0 += __shfl_xor_sync(0xffffffffu, ps0, 1);
        ps0 += __shfl_xor_sync(0xffffffffu, ps0, 2);
        ps1 += __shfl_xor_sync(0xffffffffu, ps1, 1);
        ps1 += __shfl_xor_sync(0xffffffffu, ps1, 2);
        if (tig == 0) {
            sumbuf[warp_n * 64 + m0 + g]     = ps0;
            sumbuf[warp_n * 64 + m0 + g + 8] = ps1;
        }

#pragma unroll
        for (int nt = 0; nt < 4; nt++) {
            const int pc = nb + nt * 8 + 2 * tig;
            *(float2*)&Pbuf[(m0 + g) * AST + pc]     = make_float2(sacc[nt][0], sacc[nt][1]);
            *(float2*)&Pbuf[(m0 + g + 8) * AST + pc] = make_float2(sacc[nt][2], sacc[nt][3]);
            oacc[nt][0] *= sc0; oacc[nt][1] *= sc0;
            oacc[nt][2] *= sc1; oacc[nt][3] *= sc1;
        }
        __syncthreads();   // (D)

        li0 = li0 * sc0 + sumbuf[m0 + g] + sumbuf[64 + m0 + g];
        li1 = li1 * sc1 + sumbuf[m0 + g + 8] + sumbuf[64 + m0 + g + 8];

#pragma unroll
        for (int k8 = 0; k8 < 8; k8++) {
            const int kb = k8 * 8;
            float f0 = Pbuf[(m0 + g) * AST + kb + tig];
            float f1 = Pbuf[(m0 + g + 8) * AST + kb + tig];
            float f2 = Pbuf[(m0 + g) * AST + kb + tig + 4];
            float f3 = Pbuf[(m0 + g + 8) * AST + kb + tig + 4];
            float h0 = tf32r(f0), h1 = tf32r(f1), h2 = tf32r(f2), h3 = tf32r(f3);
            uint32_t ph0 = __float_as_uint(h0), ph1 = __float_as_uint(h1);
            uint32_t ph2 = __float_as_uint(h2), ph3 = __float_as_uint(h3);
            uint32_t pl0 = __float_as_uint(tf32r(f0 - h0));
            uint32_t pl1 = __float_as_uint(tf32r(f1 - h1));
            uint32_t pl2 = __float_as_uint(tf32r(f2 - h2));
            uint32_t pl3 = __float_as_uint(tf32r(f3 - h3));
#pragma unroll
            for (int nt = 0; nt < 4; nt++) {
                const int cn = nb + nt * 8 + g;
                uint32_t vh0 = __float_as_uint(Vhi[(kb + tig) * AST + cn]);
                uint32_t vh1 = __float_as_uint(Vhi[(kb + tig + 4) * AST + cn]);
                uint32_t vl0 = __float_as_uint(Vlo[(kb + tig) * AST + cn]);
                uint32_t vl1 = __float_as_uint(Vlo[(kb + tig + 4) * AST + cn]);
                mma_tf32(oacc[nt][0], oacc[nt][1], oacc[nt][2], oacc[nt][3],
                         ph0, ph1, ph2, ph3, vh0, vh1);
                mma_tf32(oacc[nt][0], oacc[nt][1], oacc[nt][2], oacc[nt][3],
                         ph0, ph1, ph2, ph3, vl0, vl1);
                mma_tf32(oacc[nt][0], oacc[nt][1], oacc[nt][2], oacc[nt][3],
                         pl0, pl1, pl2, pl3, vh0, vh1);
            }
        }
    }

    float* Ob = O + (size_t)b * L_ * D_ + h * HD_;
    const float inv0 = 1.0f / li0;
    const float inv1 = 1.0f / li1;
#pragma unroll
    for (int nt = 0; nt < 4; nt++) {
        const int col = nb + nt * 8 + 2 * tig;
        *(float2*)(Ob + (size_t)(q0 + m0 + g) * D_ + col) =
            make_float2(oacc[nt][0] * inv0, oacc[nt][1] * inv0);
        *(float2*)(Ob + (size_t)(q0 + m0 + g + 8) * D_ + col) =
            make_float2(oacc[nt][2] * inv1, oacc[nt][3] * inv1);
    }
}

// ---------------------------------------------------------------------------
// Launch
// ---------------------------------------------------------------------------
extern "C" void kernel_launch(void* const* d_in, const int* in_sizes, int n_in,
                              void* d_out, int out_size)
{
    (void)in_sizes; (void)n_in; (void)out_size;
    const float* query = (const float*)d_in[0];
    const float* key   = (const float*)d_in[1];
    const float* value = (const float*)d_in[2];
    const float* Wq    = (const float*)d_in[3];
    const float* bq    = (const float*)d_in[4];
    const float* Wk    = (const float*)d_in[5];
    const float* bk    = (const float*)d_in[6];
    const float* Wv    = (const float*)d_in[7];
    const float* bv    = (const float*)d_in[8];
    const float* Wo    = (const float*)d_in[9];
    const float* bo    = (const float*)d_in[10];
    float* out = (float*)d_out;

    float *Qb, *Kb, *Vb, *Cb;
    uint32_t *asp, *wsp;
    cudaGetSymbolAddress((void**)&Qb, g_Q);
    cudaGetSymbolAddress((void**)&Kb, g_K);
    cudaGetSymbolAddress((void**)&Vb, g_V);
    cudaGetSymbolAddress((void**)&Cb, g_C);
    cudaGetSymbolAddress((void**)&asp, g_asp);
    cudaGetSymbolAddress((void**)&wsp, g_wsp);

    const size_t APL = (size_t)M_TOT * 512;     // activation plane (u32)
    const size_t WPL = (size_t)1024 * 512;      // weight plane (u32)
    uint32_t* aQ = asp + 0 * 3 * APL;
    uint32_t* aK = asp + 1 * 3 * APL;
    uint32_t* aV = asp + 2 * 3 * APL;
    uint32_t* aC = asp + 3 * 3 * APL;
    uint32_t* wQ = wsp + 0 * 3 * WPL;
    uint32_t* wK = wsp + 1 * 3 * WPL;
    uint32_t* wV = wsp + 2 * 3 * WPL;
    uint32_t* wO = wsp + 3 * 3 * WPL;

    const int gemm_smem = 4 * GBW * 4;             // 57344 bytes
    cudaFuncSetAttribute(gemm_bf16s_bias,
                         cudaFuncAttributeMaxDynamicSharedMemorySize, gemm_smem);
    const int attn_smem = (6 * ATILE + 256) * 4;   // 105472 bytes
    cudaFuncSetAttribute(attn_tc,
                         cudaFuncAttributeMaxDynamicSharedMemorySize, attn_smem);

    const int nA = M_TOT * 512;
    const int nW = 1024 * 512;
    split3_kernel<<<nA / 256, 256>>>(query, aQ, APL, nA);
    split3_kernel<<<nA / 256, 256>>>(key,   aK, APL, nA);
    split3_kernel<<<nA / 256, 256>>>(value, aV, APL, nA);
    split3_kernel<<<nW / 256, 256>>>(Wq, wQ, WPL, nW);
    split3_kernel<<<nW / 256, 256>>>(Wk, wK, WPL, nW);
    split3_kernel<<<nW / 256, 256>>>(Wv, wV, WPL, nW);
    split3_kernel<<<nW / 256, 256>>>(Wo, wO, WPL, nW);

    dim3 gemm_grid(D_ / 128, M_TOT / 128);  // (8, 64)
    gemm_bf16s_bias<<<gemm_grid, 256, gemm_smem>>>(aQ, wQ, APL, WPL, bq, Qb);
    gemm_bf16s_bias<<<gemm_grid, 256, gemm_smem>>>(aK, wK, APL, WPL, bk, Kb);
    gemm_bf16s_bias<<<gemm_grid, 256, gemm_smem>>>(aV, wV, APL, WPL, bv, Vb);

    attn_tc<<<dim3(L_ / 64, B_ * H_), 256, attn_smem>>>(Qb, Kb, Vb, Cb);

    split3_kernel<<<nA / 256, 256>>>(Cb, aC, APL, nA);
    gemm_bf16s_bias<<<gemm_grid, 256, gemm_smem>>>(aC, wO, APL, WPL, bo, out);
}

// round 16
// speedup vs baseline: 1.2037x; 1.2037x over previous
#include <cuda_runtime.h>
#include <cuda_bf16.h>
#include <math.h>
#include <stdint.h>

// Problem constants
#define B_  4
#define L_  2048
#define D_  1024
#define H_  16
#define HD_ 64
#define M_TOT (B_ * L_)          // 8192 rows for all projection GEMMs

// ---------------------------------------------------------------------------
// Scratch (allocation-free rule: __device__ globals)
// ---------------------------------------------------------------------------
__device__ float g_Q[(size_t)M_TOT * D_];
__device__ float g_K[(size_t)M_TOT * D_];
__device__ float g_V[(size_t)M_TOT * D_];
__device__ float g_C[(size_t)M_TOT * D_];
// bf16 2-term split planes (packed 2 bf16/u32 along K): V + ctx activations,
// Wv + Wo weights.
__device__ uint32_t g_asp2[(size_t)2 * 2 * M_TOT * 512];
__device__ uint32_t g_wsp2[(size_t)2 * 2 * 1024 * 512];

// ---------------------------------------------------------------------------
// split2: fp32 -> 2 bf16 planes, packed 2-per-u32 along K. x ~= b0 + b1.
// ---------------------------------------------------------------------------
__global__ void split2_kernel(const float* __restrict__ X, uint32_t* __restrict__ P,
                              size_t plane, int n)
{
    int i = blockIdx.x * blockDim.x + threadIdx.x;
    if (i >= n) return;
    float2 v = *(const float2*)(X + (size_t)2 * i);
    unsigned short a0, a1, b0, b1;
    {
        float x = v.x;
        __nv_bfloat16 h = __float2bfloat16_rn(x); a0 = __bfloat16_as_ushort(h);
        float r = x - __bfloat162float(h);
        h = __float2bfloat16_rn(r); a1 = __bfloat16_as_ushort(h);
    }
    {
        float x = v.y;
        __nv_bfloat16 h = __float2bfloat16_rn(x); b0 = __bfloat16_as_ushort(h);
        float r = x - __bfloat162float(h);
        h = __float2bfloat16_rn(r); b1 = __bfloat16_as_ushort(h);
    }
    P[i]         = (uint32_t)a0 | ((uint32_t)b0 << 16);
    P[plane + i] = (uint32_t)a1 | ((uint32_t)b1 << 16);
}

// ---------------------------------------------------------------------------
// MMA helpers
// ---------------------------------------------------------------------------
__device__ __forceinline__ void mma_bf16(
    float& c0, float& c1, float& c2, float& c3,
    uint32_t a0, uint32_t a1, uint32_t a2, uint32_t a3,
    uint32_t b0, uint32_t b1)
{
    asm volatile(
        "mma.sync.aligned.m16n8k16.row.col.f32.bf16.bf16.f32 "
        "{%0,%1,%2,%3}, {%4,%5,%6,%7}, {%8,%9}, {%0,%1,%2,%3};\n"
        : "+f"(c0), "+f"(c1), "+f"(c2), "+f"(c3)
        : "r"(a0), "r"(a1), "r"(a2), "r"(a3), "r"(b0), "r"(b1));
}
__device__ __forceinline__ float tf32r(float x) {
    uint32_t r;
    asm("cvt.rna.tf32.f32 %0, %1;" : "=r"(r) : "f"(x));
    return __uint_as_float(r);
}
__device__ __forceinline__ void mma_tf32(
    float& c0, float& c1, float& c2, float& c3,
    uint32_t a0, uint32_t a1, uint32_t a2, uint32_t a3,
    uint32_t b0, uint32_t b1)
{
    asm volatile(
        "mma.sync.aligned.m16n8k8.row.col.f32.tf32.tf32.f32 "
        "{%0,%1,%2,%3}, {%4,%5,%6,%7}, {%8,%9}, {%0,%1,%2,%3};\n"
        : "+f"(c0), "+f"(c1), "+f"(c2), "+f"(c3)
        : "r"(a0), "r"(a1), "r"(a2), "r"(a3), "r"(b0), "r"(b1));
}

// ---------------------------------------------------------------------------
// GEMM A: tf32 split (hh+hl+lh), pre-split hi/lo SMEM — EXACT R8 measured
// kernel (part of the 2682us run). Used for Q and K projections (softmax-
// amplified error path, ~2^-22 residual required).
// ---------------------------------------------------------------------------
#define TST 20
#define GBUF (128 * TST)

__global__ __launch_bounds__(256, 2) void gemm_tf32s_bias(
    const float* __restrict__ A, const float* __restrict__ W,
    const float* __restrict__ bias, float* __restrict__ C,
    int M, int N, int K)
{
    extern __shared__ float dsm[];
    float* Ahi = dsm;
    float* Alo = dsm + 2 * GBUF;
    float* Whi = dsm + 4 * GBUF;
    float* Wlo = dsm + 6 * GBUF;

    const int tid    = threadIdx.x;
    const int warp   = tid >> 5;
    const int lane   = tid & 31;
    const int g      = lane >> 2;
    const int tig    = lane & 3;
    const int warp_m = warp >> 2;
    const int warp_n = warp & 3;

    const int m0 = blockIdx.y * 128;
    const int n0 = blockIdx.x * 128;

    const int lrow0 = tid >> 2;
    const int lrow1 = lrow0 + 64;
    const int lkq   = (tid & 3) << 2;

    const float* Ar0 = A + (size_t)(m0 + lrow0) * K + lkq;
    const float* Ar1 = A + (size_t)(m0 + lrow1) * K + lkq;
    const float* Wr0 = W + (size_t)(n0 + lrow0) * K + lkq;
    const float* Wr1 = W + (size_t)(n0 + lrow1) * K + lkq;

    float c[4][4][4];
#pragma unroll
    for (int i = 0; i < 4; i++)
#pragma unroll
        for (int j = 0; j < 4; j++)
#pragma unroll
            for (int r = 0; r < 4; r++) c[i][j][r] = 0.0f;

#define SPLIT_STORE(HI, LO, st, row, kq, v)                                   \
    do {                                                                      \
        float4 _h = make_float4(tf32r((v).x), tf32r((v).y),                   \
                                tf32r((v).z), tf32r((v).w));                  \
        (HI)[(st) * GBUF + (row) * TST + (kq) + 0] = _h.x;                    \
        (HI)[(st) * GBUF + (row) * TST + (kq) + 1] = _h.y;                    \
        (HI)[(st) * GBUF + (row) * TST + (kq) + 2] = _h.z;                    \
        (HI)[(st) * GBUF + (row) * TST + (kq) + 3] = _h.w;                    \
        (LO)[(st) * GBUF + (row) * TST + (kq) + 0] = tf32r((v).x - _h.x);     \
        (LO)[(st) * GBUF + (row) * TST + (kq) + 1] = tf32r((v).y - _h.y);     \
        (LO)[(st) * GBUF + (row) * TST + (kq) + 2] = tf32r((v).z - _h.z);     \
        (LO)[(st) * GBUF + (row) * TST + (kq) + 3] = tf32r((v).w - _h.w);     \
    } while (0)

    {
        float4 a0 = *(const float4*)(Ar0);
        float4 a1 = *(const float4*)(Ar1);
        float4 w0 = *(const float4*)(Wr0);
        float4 w1 = *(const float4*)(Wr1);
        SPLIT_STORE(Ahi, Alo, 0, lrow0, lkq, a0);
        SPLIT_STORE(Ahi, Alo, 0, lrow1, lkq, a1);
        SPLIT_STORE(Whi, Wlo, 0, lrow0, lkq, w0);
        SPLIT_STORE(Whi, Wlo, 0, lrow1, lkq, w1);
    }
    __syncthreads();

    const int NT = K / 16;
    for (int kt = 0; kt < NT; kt++) {
        const int cur = kt & 1;
        const bool have_next = (kt + 1 < NT);

        float4 na0, na1, nw0, nw1;
        if (have_next) {
            const int kb = (kt + 1) * 16;
            na0 = *(const float4*)(Ar0 + kb);
            na1 = *(const float4*)(Ar1 + kb);
            nw0 = *(const float4*)(Wr0 + kb);
            nw1 = *(const float4*)(Wr1 + kb);
        }

#pragma unroll
        for (int ks = 0; ks < 2; ks++) {
            const int k = ks * 8;
            uint32_t ah[4][4], al[4][4];
#pragma unroll
            for (int mt = 0; mt < 4; mt++) {
                const int r = warp_m * 64 + mt * 16 + g;
                const int ba = cur * GBUF + r * TST + k + tig;
                ah[mt][0] = __float_as_uint(Ahi[ba]);
                ah[mt][1] = __float_as_uint(Ahi[ba + 8 * TST]);
                ah[mt][2] = __float_as_uint(Ahi[ba + 4]);
                ah[mt][3] = __float_as_uint(Ahi[ba + 8 * TST + 4]);
                al[mt][0] = __float_as_uint(Alo[ba]);
                al[mt][1] = __float_as_uint(Alo[ba + 8 * TST]);
                al[mt][2] = __float_as_uint(Alo[ba + 4]);
                al[mt][3] = __float_as_uint(Alo[ba + 8 * TST + 4]);
            }
#pragma unroll
            for (int nt = 0; nt < 4; nt++) {
                const int n = warp_n * 32 + nt * 8 + g;
                const int bb = cur * GBUF + n * TST + k + tig;
                uint32_t bh0 = __float_as_uint(Whi[bb]);
                uint32_t bh1 = __float_as_uint(Whi[bb + 4]);
                uint32_t bl0 = __float_as_uint(Wlo[bb]);
                uint32_t bl1 = __float_as_uint(Wlo[bb + 4]);
#pragma unroll
                for (int mt = 0; mt < 4; mt++) {
                    mma_tf32(c[mt][nt][0], c[mt][nt][1], c[mt][nt][2], c[mt][nt][3],
                             ah[mt][0], ah[mt][1], ah[mt][2], ah[mt][3], bh0, bh1);
                    mma_tf32(c[mt][nt][0], c[mt][nt][1], c[mt][nt][2], c[mt][nt][3],
                             ah[mt][0], ah[mt][1], ah[mt][2], ah[mt][3], bl0, bl1);
                    mma_tf32(c[mt][nt][0], c[mt][nt][1], c[mt][nt][2], c[mt][nt][3],
                             al[mt][0], al[mt][1], al[mt][2], al[mt][3], bh0, bh1);
                }
            }
        }

        if (have_next) {
            const int nbuf = 1 - cur;
            SPLIT_STORE(Ahi, Alo, nbuf, lrow0, lkq, na0);
            SPLIT_STORE(Ahi, Alo, nbuf, lrow1, lkq, na1);
            SPLIT_STORE(Whi, Wlo, nbuf, lrow0, lkq, nw0);
            SPLIT_STORE(Whi, Wlo, nbuf, lrow1, lkq, nw1);
            __syncthreads();
        }
    }

#pragma unroll
    for (int nt = 0; nt < 4; nt++) {
        const int col = n0 + warp_n * 32 + nt * 8 + 2 * tig;
        const float b0v = bias[col];
        const float b1v = bias[col + 1];
#pragma unroll
        for (int mt = 0; mt < 4; mt++) {
            const int row = m0 + warp_m * 64 + mt * 16 + g;
            *(float2*)(C + (size_t)row * N + col) =
                make_float2(c[mt][nt][0] + b0v, c[mt][nt][1] + b1v);
            *(float2*)(C + (size_t)(row + 8) * N + col) =
                make_float2(c[mt][nt][2] + b0v, c[mt][nt][3] + b1v);
        }
    }
#undef SPLIT_STORE
}

// ---------------------------------------------------------------------------
// GEMM B: bf16 2-term split (products 00,01,10) — HALF the MMA count.
// Used for V projection and output projection (linear error paths, ~2-3e-5).
// Pre-split packed planes; single-pass fragments; TSW2=20 (banks all-distinct:
// (20g+tig)%32); __launch_bounds__(256,2); 40960 B dynamic SMEM.
// ---------------------------------------------------------------------------
#define TSW2 20
#define GBW2 (128 * TSW2)          // 2560 words per matrix per buffer

__global__ __launch_bounds__(256, 2) void gemm_bf16_2t(
    const uint32_t* __restrict__ Asp, const uint32_t* __restrict__ Wsp,
    size_t PA, size_t PW,
    const float* __restrict__ bias, float* __restrict__ C)
{
    extern __shared__ uint32_t gsm[];
    uint32_t* As = gsm;              // [2][GBW2]
    uint32_t* Ws = gsm + 2 * GBW2;   // [2][GBW2]

    const int tid    = threadIdx.x;
    const int warp   = tid >> 5;
    const int lane   = tid & 31;
    const int g      = lane >> 2;
    const int tig    = lane & 3;
    const int warp_m = warp >> 2;
    const int warp_n = warp & 3;

    const int m0 = blockIdx.y * 128;
    const int n0 = blockIdx.x * 128;

    const int srow = tid >> 1;            // 0..127
    const int sw   = (tid & 1) * 4;       // word 0 or 4 of each 8-word plane row

    float c[4][4][4];
#pragma unroll
    for (int i = 0; i < 4; i++)
#pragma unroll
        for (int j = 0; j < 4; j++)
#pragma unroll
            for (int r = 0; r < 4; r++) c[i][j][r] = 0.0f;

    // Prologue: stage tile 0 (2 planes x 1 uint4 per matrix per thread)
#pragma unroll
    for (int t = 0; t < 2; t++) {
        *(uint4*)&As[srow * TSW2 + t * 8 + sw] =
            *(const uint4*)(Asp + t * PA + (size_t)(m0 + srow) * 512 + sw);
        *(uint4*)&Ws[srow * TSW2 + t * 8 + sw] =
            *(const uint4*)(Wsp + t * PW + (size_t)(n0 + srow) * 512 + sw);
    }
    __syncthreads();

    for (int kt = 0; kt < 64; kt++) {
        const int cur = kt & 1;
        const bool have_next = (kt + 1 < 64);

        uint4 na[2], nw[2];
        if (have_next) {
            const int kw = (kt + 1) * 8 + sw;
#pragma unroll
            for (int t = 0; t < 2; t++) {
                na[t] = *(const uint4*)(Asp + t * PA + (size_t)(m0 + srow) * 512 + kw);
                nw[t] = *(const uint4*)(Wsp + t * PW + (size_t)(n0 + srow) * 512 + kw);
            }
        }

        const uint32_t* Ab = As + cur * GBW2;
        const uint32_t* Wb = Ws + cur * GBW2;

        uint32_t a0f[4][4], a1f[4][4];
#pragma unroll
        for (int mt = 0; mt < 4; mt++) {
            const int r  = warp_m * 64 + mt * 16 + g;
            const int ba = r * TSW2 + tig;
            a0f[mt][0] = Ab[ba];
            a0f[mt][1] = Ab[ba + 8 * TSW2];
            a0f[mt][2] = Ab[ba + 4];
            a0f[mt][3] = Ab[ba + 8 * TSW2 + 4];
            a1f[mt][0] = Ab[ba + 8];
            a1f[mt][1] = Ab[ba + 8 * TSW2 + 8];
            a1f[mt][2] = Ab[ba + 12];
            a1f[mt][3] = Ab[ba + 8 * TSW2 + 12];
        }
#pragma unroll
        for (int nt = 0; nt < 4; nt++) {
            const int n  = warp_n * 32 + nt * 8 + g;
            const int bb = n * TSW2 + tig;
            uint32_t b00 = Wb[bb],     b01 = Wb[bb + 4];
            uint32_t b10 = Wb[bb + 8], b11 = Wb[bb + 12];
#pragma unroll
            for (int mt = 0; mt < 4; mt++) {
                mma_bf16(c[mt][nt][0], c[mt][nt][1], c[mt][nt][2], c[mt][nt][3],
                         a0f[mt][0], a0f[mt][1], a0f[mt][2], a0f[mt][3], b00, b01);
                mma_bf16(c[mt][nt][0], c[mt][nt][1], c[mt][nt][2], c[mt][nt][3],
                         a0f[mt][0], a0f[mt][1], a0f[mt][2], a0f[mt][3], b10, b11);
                mma_bf16(c[mt][nt][0], c[mt][nt][1], c[mt][nt][2], c[mt][nt][3],
                         a1f[mt][0], a1f[mt][1], a1f[mt][2], a1f[mt][3], b00, b01);
            }
        }

        if (have_next) {
            const int nb = 1 - cur;
#pragma unroll
            for (int t = 0; t < 2; t++) {
                *(uint4*)&As[nb * GBW2 + srow * TSW2 + t * 8 + sw] = na[t];
                *(uint4*)&Ws[nb * GBW2 + srow * TSW2 + t * 8 + sw] = nw[t];
            }
            __syncthreads();
        }
    }

#pragma unroll
    for (int nt = 0; nt < 4; nt++) {
        const int col = n0 + warp_n * 32 + nt * 8 + 2 * tig;
        const float b0v = bias[col];
        const float b1v = bias[col + 1];
#pragma unroll
        for (int mt = 0; mt < 4; mt++) {
            const int row = m0 + warp_m * 64 + mt * 16 + g;
            *(float2*)(C + (size_t)row * 1024 + col) =
                make_float2(c[mt][nt][0] + b0v, c[mt][nt][1] + b1v);
            *(float2*)(C + (size_t)(row + 8) * 1024 + col) =
                make_float2(c[mt][nt][2] + b0v, c[mt][nt][3] + b1v);
        }
    }
}

// ---------------------------------------------------------------------------
// Flash attention, split-tf32 mma.sync — measured-best R7 form (2682us run).
// ---------------------------------------------------------------------------
#define AST 68
#define ATILE 4352

__global__ __launch_bounds__(256) void attn_tc(
    const float* __restrict__ Q, const float* __restrict__ K,
    const float* __restrict__ V, float* __restrict__ O)
{
    extern __shared__ float sm[];
    float* Qhi = sm;
    float* Qlo = sm + ATILE;
    float* Khi = sm + 2 * ATILE;
    float* Klo = sm + 3 * ATILE;
    float* Vhi = sm + 4 * ATILE;
    float* Vlo = sm + 5 * ATILE;
    float* Pbuf = Khi;
    float* maxbuf = sm + 6 * ATILE;
    float* sumbuf = maxbuf + 128;

    const int tid  = threadIdx.x;
    const int warp = tid >> 5;
    const int lane = tid & 31;
    const int g    = lane >> 2;
    const int tig  = lane & 3;
    const int warp_m = warp >> 1;
    const int warp_n = warp & 1;
    const int m0 = warp_m * 16;
    const int nb = warp_n * 32;

    const int q0 = blockIdx.x * 64;
    const int bh = blockIdx.y;
    const int b  = bh / H_;
    const int h  = bh % H_;

    const float* Qb = Q + (size_t)b * L_ * D_ + h * HD_;
    const float* Kb = K + (size_t)b * L_ * D_ + h * HD_;
    const float* Vb = V + (size_t)b * L_ * D_ + h * HD_;

#pragma unroll
    for (int t = 0; t < 4; t++) {
        int idx = tid + t * 256;
        int row = idx >> 4;
        int d0  = (idx & 15) << 2;
        float4 v = *(const float4*)(Qb + (size_t)(q0 + row) * D_ + d0);
        v.x *= 0.125f; v.y *= 0.125f; v.z *= 0.125f; v.w *= 0.125f;
        float4 hi = make_float4(tf32r(v.x), tf32r(v.y), tf32r(v.z), tf32r(v.w));
        float4 lo = make_float4(tf32r(v.x - hi.x), tf32r(v.y - hi.y),
                                tf32r(v.z - hi.z), tf32r(v.w - hi.w));
        *(float4*)&Qhi[row * AST + d0] = hi;
        *(float4*)&Qlo[row * AST + d0] = lo;
    }

    float mi0 = -INFINITY, mi1 = -INFINITY, li0 = 0.0f, li1 = 0.0f;
    float oacc[4][4];
#pragma unroll
    for (int nt = 0; nt < 4; nt++)
#pragma unroll
        for (int r = 0; r < 4; r++) oacc[nt][r] = 0.0f;

    for (int kv0 = 0; kv0 < L_; kv0 += 64) {
        __syncthreads();   // (A)

#pragma unroll
        for (int t = 0; t < 4; t++) {
            int idx = tid + t * 256;
            int row = idx >> 4;
            int d0  = (idx & 15) << 2;
            float4 kv = *(const float4*)(Kb + (size_t)(kv0 + row) * D_ + d0);
            float4 khi = make_float4(tf32r(kv.x), tf32r(kv.y), tf32r(kv.z), tf32r(kv.w));
            float4 klo = make_float4(tf32r(kv.x - khi.x), tf32r(kv.y - khi.y),
                                     tf32r(kv.z - khi.z), tf32r(kv.w - khi.w));
            *(float4*)&Khi[row * AST + d0] = khi;
            *(float4*)&Klo[row * AST + d0] = klo;
            float4 vv = *(const float4*)(Vb + (size_t)(kv0 + row) * D_ + d0);
            float4 vhi = make_float4(tf32r(vv.x), tf32r(vv.y), tf32r(vv.z), tf32r(vv.w));
            float4 vlo = make_float4(tf32r(vv.x - vhi.x), tf32r(vv.y - vhi.y),
                                     tf32r(vv.z - vhi.z), tf32r(vv.w - vhi.w));
            *(float4*)&Vhi[row * AST + d0] = vhi;
            *(float4*)&Vlo[row * AST + d0] = vlo;
        }
        __syncthreads();   // (B)

        float sacc[4][4];
#pragma unroll
        for (int nt = 0; nt < 4; nt++)
#pragma unroll
            for (int r = 0; r < 4; r++) sacc[nt][r] = 0.0f;

#pragma unroll
        for (int k8 = 0; k8 < 8; k8++) {
            const int kb = k8 * 8;
            const int ra = (m0 + g) * AST + kb + tig;
            const int rb = (m0 + g + 8) * AST + kb + tig;
            uint32_t ah0 = __float_as_uint(Qhi[ra]);
            uint32_t ah1 = __float_as_uint(Qhi[rb]);
            uint32_t ah2 = __float_as_uint(Qhi[ra + 4]);
            uint32_t ah3 = __float_as_uint(Qhi[rb + 4]);
            uint32_t al0 = __float_as_uint(Qlo[ra]);
            uint32_t al1 = __float_as_uint(Qlo[rb]);
            uint32_t al2 = __float_as_uint(Qlo[ra + 4]);
            uint32_t al3 = __float_as_uint(Qlo[rb + 4]);
#pragma unroll
            for (int nt = 0; nt < 4; nt++) {
                const int rn = (nb + nt * 8 + g) * AST + kb + tig;
                uint32_t bh0 = __float_as_uint(Khi[rn]);
                uint32_t bh1 = __float_as_uint(Khi[rn + 4]);
                uint32_t bl0 = __float_as_uint(Klo[rn]);
                uint32_t bl1 = __float_as_uint(Klo[rn + 4]);
                mma_tf32(sacc[nt][0], sacc[nt][1], sacc[nt][2], sacc[nt][3],
                         ah0, ah1, ah2, ah3, bh0, bh1);
                mma_tf32(sacc[nt][0], sacc[nt][1], sacc[nt][2], sacc[nt][3],
                         ah0, ah1, ah2, ah3, bl0, bl1);
                mma_tf32(sacc[nt][0], sacc[nt][1], sacc[nt][2], sacc[nt][3],
                         al0, al1, al2, al3, bh0, bh1);
            }
        }

        float mx0 = -INFINITY, mx1 = -INFINITY;
#pragma unroll
        for (int nt = 0; nt < 4; nt++) {
            mx0 = fmaxf(mx0, fmaxf(sacc[nt][0], sacc[nt][1]));
            mx1 = fmaxf(mx1, fmaxf(sacc[nt][2], sacc[nt][3]));
        }
        mx0 = fmaxf(mx0, __shfl_xor_sync(0xffffffffu, mx0, 1));
        mx0 = fmaxf(mx0, __shfl_xor_sync(0xffffffffu, mx0, 2));
        mx1 = fmaxf(mx1, __shfl_xor_sync(0xffffffffu, mx1, 1));
        mx1 = fmaxf(mx1, __shfl_xor_sync(0xffffffffu, mx1, 2));
        if (tig == 0) {
            maxbuf[warp_n * 64 + m0 + g]     = mx0;
            maxbuf[warp_n * 64 + m0 + g + 8] = mx1;
        }
        __syncthreads();   // (C)

        const float mn0 = fmaxf(mi0, fmaxf(maxbuf[m0 + g], maxbuf[64 + m0 + g]));
        const float mn1 = fmaxf(mi1, fmaxf(maxbuf[m0 + g + 8], maxbuf[64 + m0 + g + 8]));
        const float sc0 = __expf(mi0 - mn0);
        const float sc1 = __expf(mi1 - mn1);
        mi0 = mn0; mi1 = mn1;

        float ps0 = 0.0f, ps1 = 0.0f;
#pragma unroll
        for (int nt = 0; nt < 4; nt++) {
            sacc[nt][0] = __expf(sacc[nt][0] - mn0);
            sacc[nt][1] = __expf(sacc[nt][1] - mn0);
            sacc[nt][2] = __expf(sacc[nt][2] - mn1);
            sacc[nt][3] = __expf(sacc[nt][3] - mn1);
            ps0 += sacc[nt][0] + sacc[nt][1];
            ps1 += sacc[nt][2] + sacc[nt][3];
        }
        ps0 += __shfl_xor_sync(0xffffffffu, ps0, 1);
        ps0 += __shfl_xor_sync(0xffffffffu, ps0, 2);
        ps1 += __shfl_xor_sync(0xffffffffu, ps1, 1);
        ps1 += __shfl_xor_sync(0xffffffffu, ps1, 2);
        if (tig == 0) {
            sumbuf[warp_n * 64 + m0 + g]     = ps0;
            sumbuf[warp_n * 64 + m0 + g + 8] = ps1;
        }

#pragma unroll
        for (int nt = 0; nt < 4; nt++) {
            const int pc = nb + nt * 8 + 2 * tig;
            *(float2*)&Pbuf[(m0 + g) * AST + pc]     = make_float2(sacc[nt][0], sacc[nt][1]);
            *(float2*)&Pbuf[(m0 + g + 8) * AST + pc] = make_float2(sacc[nt][2], sacc[nt][3]);
            oacc[nt][0] *= sc0; oacc[nt][1] *= sc0;
            oacc[nt][2] *= sc1; oacc[nt][3] *= sc1;
        }
        __syncthreads();   // (D)

        li0 = li0 * sc0 + sumbuf[m0 + g] + sumbuf[64 + m0 + g];
        li1 = li1 * sc1 + sumbuf[m0 + g + 8] + sumbuf[64 + m0 + g + 8];

#pragma unroll
        for (int k8 = 0; k8 < 8; k8++) {
            const int kb = k8 * 8;
            float f0 = Pbuf[(m0 + g) * AST + kb + tig];
            float f1 = Pbuf[(m0 + g + 8) * AST + kb + tig];
            float f2 = Pbuf[(m0 + g) * AST + kb + tig + 4];
            float f3 = Pbuf[(m0 + g + 8) * AST + kb + tig + 4];
            float h0 = tf32r(f0), h1 = tf32r(f1), h2 = tf32r(f2), h3 = tf32r(f3);
            uint32_t ph0 = __float_as_uint(h0), ph1 = __float_as_uint(h1);
            uint32_t ph2 = __float_as_uint(h2), ph3 = __float_as_uint(h3);
            uint32_t pl0 = __float_as_uint(tf32r(f0 - h0));
            uint32_t pl1 = __float_as_uint(tf32r(f1 - h1));
            uint32_t pl2 = __float_as_uint(tf32r(f2 - h2));
            uint32_t pl3 = __float_as_uint(tf32r(f3 - h3));
#pragma unroll
            for (int nt = 0; nt < 4; nt++) {
                const int cn = nb + nt * 8 + g;
                uint32_t vh0 = __float_as_uint(Vhi[(kb + tig) * AST + cn]);
                uint32_t vh1 = __float_as_uint(Vhi[(kb + tig + 4) * AST + cn]);
                uint32_t vl0 = __float_as_uint(Vlo[(kb + tig) * AST + cn]);
                uint32_t vl1 = __float_as_uint(Vlo[(kb + tig + 4) * AST + cn]);
                mma_tf32(oacc[nt][0], oacc[nt][1], oacc[nt][2], oacc[nt][3],
                         ph0, ph1, ph2, ph3, vh0, vh1);
                mma_tf32(oacc[nt][0], oacc[nt][1], oacc[nt][2], oacc[nt][3],
                         ph0, ph1, ph2, ph3, vl0, vl1);
                mma_tf32(oacc[nt][0], oacc[nt][1], oacc[nt][2], oacc[nt][3],
                         pl0, pl1, pl2, pl3, vh0, vh1);
            }
        }
    }

    float* Ob = O + (size_t)b * L_ * D_ + h * HD_;
    const float inv0 = 1.0f / li0;
    const float inv1 = 1.0f / li1;
#pragma unroll
    for (int nt = 0; nt < 4; nt++) {
        const int col = nb + nt * 8 + 2 * tig;
        *(float2*)(Ob + (size_t)(q0 + m0 + g) * D_ + col) =
            make_float2(oacc[nt][0] * inv0, oacc[nt][1] * inv0);
        *(float2*)(Ob + (size_t)(q0 + m0 + g + 8) * D_ + col) =
            make_float2(oacc[nt][2] * inv1, oacc[nt][3] * inv1);
    }
}

// ---------------------------------------------------------------------------
// Launch
// ---------------------------------------------------------------------------
extern "C" void kernel_launch(void* const* d_in, const int* in_sizes, int n_in,
                              void* d_out, int out_size)
{
    (void)in_sizes; (void)n_in; (void)out_size;
    const float* query = (const float*)d_in[0];
    const float* key   = (const float*)d_in[1];
    const float* value = (const float*)d_in[2];
    const float* Wq    = (const float*)d_in[3];
    const float* bq    = (const float*)d_in[4];
    const float* Wk    = (const float*)d_in[5];
    const float* bk    = (const float*)d_in[6];
    const float* Wv    = (const float*)d_in[7];
    const float* bv    = (const float*)d_in[8];
    const float* Wo    = (const float*)d_in[9];
    const float* bo    = (const float*)d_in[10];
    float* out = (float*)d_out;

    float *Qb, *Kb, *Vb, *Cb;
    uint32_t *asp, *wsp;
    cudaGetSymbolAddress((void**)&Qb, g_Q);
    cudaGetSymbolAddress((void**)&Kb, g_K);
    cudaGetSymbolAddress((void**)&Vb, g_V);
    cudaGetSymbolAddress((void**)&Cb, g_C);
    cudaGetSymbolAddress((void**)&asp, g_asp2);
    cudaGetSymbolAddress((void**)&wsp, g_wsp2);

    const size_t APL = (size_t)M_TOT * 512;     // activation plane (u32)
    const size_t WPL = (size_t)1024 * 512;      // weight plane (u32)
    uint32_t* aV = asp;                 // 2 planes
    uint32_t* aC = asp + 2 * APL;       // 2 planes
    uint32_t* wV = wsp;                 // 2 planes
    uint32_t* wO = wsp + 2 * WPL;       // 2 planes

    const int tf32_smem = 8 * GBUF * 4;            // 81920 bytes
    cudaFuncSetAttribute(gemm_tf32s_bias,
                         cudaFuncAttributeMaxDynamicSharedMemorySize, tf32_smem);
    const int bf16_smem = 4 * GBW2 * 4;            // 40960 bytes
    cudaFuncSetAttribute(gemm_bf16_2t,
                         cudaFuncAttributeMaxDynamicSharedMemorySize, bf16_smem);
    const int attn_smem = (6 * ATILE + 256) * 4;   // 105472 bytes
    cudaFuncSetAttribute(attn_tc,
                         cudaFuncAttributeMaxDynamicSharedMemorySize, attn_smem);

    const int nA = M_TOT * 512;
    const int nW = 1024 * 512;
    split2_kernel<<<nA / 256, 256>>>(value, aV, APL, nA);
    split2_kernel<<<nW / 256, 256>>>(Wv, wV, WPL, nW);
    split2_kernel<<<nW / 256, 256>>>(Wo, wO, WPL, nW);

    dim3 gemm_grid(D_ / 128, M_TOT / 128);  // (8, 64)
    gemm_tf32s_bias<<<gemm_grid, 256, tf32_smem>>>(query, Wq, bq, Qb, M_TOT, D_, D_);
    gemm_tf32s_bias<<<gemm_grid, 256, tf32_smem>>>(key,   Wk, bk, Kb, M_TOT, D_, D_);
    gemm_bf16_2t<<<gemm_grid, 256, bf16_smem>>>(aV, wV, APL, WPL, bv, Vb);

    attn_tc<<<dim3(L_ / 64, B_ * H_), 256, attn_smem>>>(Qb, Kb, Vb, Cb);

    split2_kernel<<<nA / 256, 256>>>(Cb, aC, APL, nA);
    gemm_bf16_2t<<<gemm_grid, 256, bf16_smem>>>(aC, wO, APL, WPL, bo, out);
}